// round 13
// baseline (speedup 1.0000x reference)
#include <cuda_runtime.h>
#include <cstdint>

#define N_ACT 300000
#define Cc 128
#define NTAPS 8
#define EPSV 1e-4f

// ---------------- scratch (device globals; zero-initialized at load) --------
__device__ float g_buf1[N_ACT * Cc];
__device__ float g_buf2[N_ACT * Cc];
__device__ int   g_pin [NTAPS * N_ACT];
__device__ int   g_pout[NTAPS * N_ACT];
__device__ int   g_cnt [NTAPS];          // self-reset by fused L2 kernel
__device__ float g_sum[Cc], g_sq[Cc];    // self-reset
__device__ float g_scale[Cc], g_shift[Cc];
__device__ int   g_done;                 // self-reset
__device__ int   g_done2;                // self-reset
__device__ int   g_flag;                 // self-reset

// ---------------- helpers ----------------------------------------------------
__device__ __forceinline__ uint32_t tf32u(float x) {
    uint32_t y;
    asm("cvt.rna.tf32.f32 %0, %1;" : "=r"(y) : "f"(x));
    return y;
}
__device__ __forceinline__ float tf32r(float x) { return __uint_as_float(tf32u(x)); }

__device__ __forceinline__ void mma8(float* d, const uint32_t* a, const uint32_t* b) {
    asm volatile(
        "mma.sync.aligned.m16n8k8.row.col.f32.tf32.tf32.f32 "
        "{%0,%1,%2,%3}, {%4,%5,%6,%7}, {%8,%9}, {%0,%1,%2,%3};"
        : "+f"(d[0]), "+f"(d[1]), "+f"(d[2]), "+f"(d[3])
        : "r"(a[0]), "r"(a[1]), "r"(a[2]), "r"(a[3]), "r"(b[0]), "r"(b[1]));
}

__device__ __forceinline__ void ldsm_x4(uint32_t* r, uint32_t addr) {
    asm volatile("ldmatrix.sync.aligned.m8n8.x4.shared.b16 {%0,%1,%2,%3}, [%4];"
                 : "=r"(r[0]), "=r"(r[1]), "=r"(r[2]), "=r"(r[3]) : "r"(addr));
}

__device__ __forceinline__ void red_add2(float* p, float a, float b) {
    asm volatile("red.relaxed.gpu.global.add.v2.f32 [%0], {%1, %2};"
                 :: "l"(p), "f"(a), "f"(b) : "memory");
}

__device__ __forceinline__ uint32_t smem_u32(const void* p) {
    uint32_t a;
    asm("{ .reg .u64 t; cvta.to.shared.u64 t, %1; cvt.u32.u64 %0, t; }" : "=r"(a) : "l"(p));
    return a;
}

// SMEM geometry
#define WP_STRIDE 132                        // float2 units per (s,tig) row
#define WP_FLOATS (16 * 4 * WP_STRIDE * 2)   // 16896 floats
#define AS_STRIDE 36                         // floats per A row (144B)
#define AS_STAGE  (128 * AS_STRIDE)

// ---------------- rulebook slice builder (runs inside layer-1 center conv) ---
__device__ void build_rulebook_slice(const int* __restrict__ nbr, int tid,
                                     int bx, int nBlocks) {
    __shared__ int scnt[NTAPS], sbase[NTAPS];
    int rowsPer = (N_ACT + nBlocks - 1) / nBlocks;
    int begin = bx * rowsPer;
    int end = begin + rowsPer;
    if (end > N_ACT) end = N_ACT;
    for (int base = begin; base < end; base += 256) {
        if (tid < NTAPS) scnt[tid] = 0;
        __syncthreads();
        int i = base + tid;
        bool act = (i < end);
        int idxv[NTAPS], lpos[NTAPS];
#pragma unroll
        for (int k = 0; k < 9; k++) {
            if (k == 4) continue;
            int t = (k < 4) ? k : k - 1;
            int idx = act ? nbr[i * 9 + k] : -1;
            idxv[t] = idx;
            lpos[t] = (idx >= 0) ? atomicAdd(&scnt[t], 1) : -1;
        }
        __syncthreads();
        if (tid < NTAPS) sbase[tid] = atomicAdd(&g_cnt[tid], scnt[tid]);
        __syncthreads();
#pragma unroll
        for (int t = 0; t < NTAPS; t++) {
            if (lpos[t] >= 0) {
                int pos = sbase[t] + lpos[t];
                g_pin [t * N_ACT + pos] = idxv[t];
                g_pout[t * N_ACT + pos] = i;
            }
        }
    }
}

// ---------------- tf32 mma.sync GEMM, cross-tile cp.async pipeline -----------
// CTA tile 128x128, K=128 in 4 chunks of 32; 8 warps (4m x 2n), 2x8 frags.
// A fragments via ldmatrix.x4 (M0..M3 = rows {0-7,8-15} x cols {k0,k0+4}).
template <bool CENTER, bool BN, bool RB>
__global__ void __launch_bounds__(256, 2) conv_mma_k(
    const float* __restrict__ in, const float* __restrict__ W,
    float* __restrict__ out, const int* __restrict__ nbr)
{
    extern __shared__ float smem[];
    float2* Wp = (float2*)smem;                        // [16][4][WP_STRIDE]
    float*  As = smem + WP_FLOATS;                     // 2 stages x 128*36
    int*    rin  = (int*)(As + 2 * AS_STAGE);          // [2][128]
    float*  ssc  = (float*)(rin + 256);
    float*  ssh  = ssc + 128;

    const uint32_t asu = smem_u32(As);

    int tid = threadIdx.x;
    int wid = tid >> 5, lane = tid & 31;
    int wm = wid >> 1, wn = wid & 1;
    int grp = lane >> 2, tig = lane & 3;

    // per-lane ldmatrix row offset: lane i -> matrix i>>3, row i&7
    int mm = lane >> 3, rr = lane & 7;
    const uint32_t a_off =
        (uint32_t)((wm * 32 + rr + (mm & 1) * 8) * 144 + (mm >> 1) * 16);

    const float* Wk;
    const int *pin = nullptr, *pout = nullptr;
    int cnt;
    if (CENTER) {
        Wk = W;
        cnt = N_ACT;
    } else {
        int tap = blockIdx.y;
        cnt = g_cnt[tap];
        int kk = (tap < 4) ? tap : tap + 1;
        Wk = W + (long)kk * Cc * Cc;
        pin  = g_pin  + (long)tap * N_ACT;
        pout = g_pout + (long)tap * N_ACT;
    }

    // Stage W[k][n] -> paired float2 layout (tf32-rounded), once per CTA.
    for (int i = tid; i < 128 * 32; i += 256) {
        int k = i >> 5, n4 = (i & 31) * 4;
        float4 v = *(const float4*)&Wk[k * Cc + n4];
        int s = k >> 3, r = k & 7, t = r & 3, half = r >> 2;
        float* d = smem + (((s * 4 + t) * WP_STRIDE + n4) * 2 + half);
        d[0] = tf32r(v.x); d[2] = tf32r(v.y); d[4] = tf32r(v.z); d[6] = tf32r(v.w);
    }
    if (BN && tid < 128) { ssc[tid] = g_scale[tid]; ssh[tid] = g_shift[tid]; }

    int numTiles = (cnt + 127) >> 7;
    int step = gridDim.x;
    int tile0 = blockIdx.x;

    auto issue = [&](int tileI, int kc, int stage, const int* rbuf, bool valid) {
        if (valid) {
            uint32_t sbase = asu + (uint32_t)stage * (AS_STAGE * 4);
            int m0 = tileI << 7;
#pragma unroll
            for (int l = 0; l < 4; l++) {
                int idx = tid + l * 256;          // 0..1023 16B-chunks
                int rloc = idx >> 3, c16 = idx & 7;
                int rg;
                if (CENTER) { int m = m0 + rloc; rg = (m < N_ACT) ? m : -1; }
                else        rg = rbuf[rloc];
                const float* src = in + (long)(rg < 0 ? 0 : rg) * Cc + kc * 32 + c16 * 4;
                uint32_t dst = sbase + (uint32_t)(rloc * 144 + c16 * 16);
                int sz = (rg >= 0) ? 16 : 0;
                asm volatile("cp.async.cg.shared.global [%0], [%1], 16, %2;"
                             :: "r"(dst), "l"(src), "r"(sz));
            }
        }
        asm volatile("cp.async.commit_group;" ::: "memory");
    };

    if (!CENTER && tid < 128) {
        int m = (tile0 << 7) + tid;
        rin[tid] = (tile0 < numTiles && m < cnt) ? pin[m] : -1;
    }
    __syncthreads();
    issue(tile0, 0, 0, rin, tile0 < numTiles);

    // rulebook prologue (layer-1 center only) — overlaps with chunk-0 loads
    if (RB) build_rulebook_slice(nbr, tid, blockIdx.x, gridDim.x);

    int it = 0;
    for (int tile = tile0; tile < numTiles; tile += step, it++) {
        int cbuf = it & 1, nbuf = cbuf ^ 1;
        int nextTile = tile + step;
        bool nextValid = nextTile < numTiles;

        if (!CENTER && tid < 128) {
            int m = (nextTile << 7) + tid;
            rin[nbuf * 128 + tid] = (nextValid && m < cnt) ? pin[m] : -1;
        }

        int ro[2][2];
        if (!CENTER) {
#pragma unroll
            for (int mt = 0; mt < 2; mt++) {
                int r0 = (tile << 7) + wm * 32 + mt * 16 + grp;
                ro[mt][0] = (r0     < cnt) ? pout[r0]     : -1;
                ro[mt][1] = (r0 + 8 < cnt) ? pout[r0 + 8] : -1;
            }
        }

        float acc[2][8][4];
#pragma unroll
        for (int a = 0; a < 2; a++)
#pragma unroll
            for (int b = 0; b < 8; b++)
#pragma unroll
                for (int c = 0; c < 4; c++) acc[a][b][c] = 0.f;

#pragma unroll
        for (int kc = 0; kc < 4; kc++) {
            if (kc < 3) issue(tile, kc + 1, (kc + 1) & 1, rin + cbuf * 128, true);
            else        issue(nextTile, 0, 0, rin + nbuf * 128, nextValid);

            asm volatile("cp.async.wait_group 1;" ::: "memory");
            __syncthreads();

            uint32_t abase = asu + (uint32_t)(kc & 1) * (AS_STAGE * 4) + a_off;

#pragma unroll
            for (int ks = 0; ks < 4; ks++) {
                int k0 = ks * 8;
                int s  = kc * 4 + ks;
                int ka = kc * 32 + k0 + tig;
                int kb = ka + 4;
                float sca = 0.f, sha = 0.f, scb = 0.f, shb = 0.f;
                if (BN) { sca = ssc[ka]; sha = ssh[ka]; scb = ssc[kb]; shb = ssh[kb]; }

                uint32_t afr[2][4], bfr[8][2];
#pragma unroll
                for (int mt = 0; mt < 2; mt++) {
                    ldsm_x4(afr[mt], abase + (uint32_t)(k0 * 4 + mt * 2304));
                    if (BN) {
                        float e0 = fmaxf(__uint_as_float(afr[mt][0]) * sca + sha, 0.f);
                        float e1 = fmaxf(__uint_as_float(afr[mt][1]) * sca + sha, 0.f);
                        float e2 = fmaxf(__uint_as_float(afr[mt][2]) * scb + shb, 0.f);
                        float e3 = fmaxf(__uint_as_float(afr[mt][3]) * scb + shb, 0.f);
                        afr[mt][0] = __float_as_uint(e0);
                        afr[mt][1] = __float_as_uint(e1);
                        afr[mt][2] = __float_as_uint(e2);
                        afr[mt][3] = __float_as_uint(e3);
                    }
                }
                const float2* wps = Wp + (s * 4 + tig) * WP_STRIDE;
#pragma unroll
                for (int nt = 0; nt < 8; nt++) {
                    int col = wn * 64 + nt * 8 + grp;
                    float2 p = wps[col];
                    bfr[nt][0] = __float_as_uint(p.x);
                    bfr[nt][1] = __float_as_uint(p.y);
                }
#pragma unroll
                for (int mt = 0; mt < 2; mt++)
#pragma unroll
                    for (int nt = 0; nt < 8; nt++)
                        mma8(acc[mt][nt], afr[mt], bfr[nt]);
            }
            __syncthreads();
        }

        int m0 = tile << 7;
#pragma unroll
        for (int mt = 0; mt < 2; mt++) {
            if (CENTER) {
                int m0r = m0 + wm * 32 + mt * 16 + grp;
                int m1r = m0r + 8;
#pragma unroll
                for (int nt = 0; nt < 8; nt++) {
                    int col = wn * 64 + nt * 8 + tig * 2;
                    if (m0r < N_ACT)
                        *(float2*)&out[(long)m0r * Cc + col] =
                            make_float2(acc[mt][nt][0], acc[mt][nt][1]);
                    if (m1r < N_ACT)
                        *(float2*)&out[(long)m1r * Cc + col] =
                            make_float2(acc[mt][nt][2], acc[mt][nt][3]);
                }
            } else {
                int ro0 = ro[mt][0], ro1 = ro[mt][1];
#pragma unroll
                for (int nt = 0; nt < 8; nt++) {
                    int col = wn * 64 + nt * 8 + tig * 2;
                    if (ro0 >= 0)
                        red_add2(&out[(long)ro0 * Cc + col], acc[mt][nt][0], acc[mt][nt][1]);
                    if (ro1 >= 0)
                        red_add2(&out[(long)ro1 * Cc + col], acc[mt][nt][2], acc[mt][nt][3]);
                }
            }
        }
    }
    asm volatile("cp.async.wait_group 0;" ::: "memory");
}

// ---------------- layer-1 stats + fused finalize (last block) ----------------
__global__ void __launch_bounds__(256) stats_k(
    const float* __restrict__ y,
    const float* __restrict__ gamma, const float* __restrict__ beta)
{
    __shared__ float ssum[8][32][4];
    __shared__ float ssq [8][32][4];
    __shared__ int lastFlag;

    int tid = threadIdx.x;
    int wid = tid >> 5;
    int c4  = tid & 31;

    float4 s = make_float4(0.f, 0.f, 0.f, 0.f);
    float4 q = make_float4(0.f, 0.f, 0.f, 0.f);
#pragma unroll 4
    for (int r = blockIdx.x * 8 + wid; r < N_ACT; r += gridDim.x * 8) {
        float4 v = *(const float4*)&y[(long)r * Cc + c4 * 4];
        s.x += v.x; s.y += v.y; s.z += v.z; s.w += v.w;
        q.x += v.x * v.x; q.y += v.y * v.y; q.z += v.z * v.z; q.w += v.w * v.w;
    }
    ssum[wid][c4][0] = s.x; ssum[wid][c4][1] = s.y;
    ssum[wid][c4][2] = s.z; ssum[wid][c4][3] = s.w;
    ssq [wid][c4][0] = q.x; ssq [wid][c4][1] = q.y;
    ssq [wid][c4][2] = q.z; ssq [wid][c4][3] = q.w;
    __syncthreads();

    if (tid < 128) {
        int cg = tid >> 2, j = tid & 3;
        float ts = 0.f, tq = 0.f;
#pragma unroll
        for (int w = 0; w < 8; w++) { ts += ssum[w][cg][j]; tq += ssq[w][cg][j]; }
        atomicAdd(&g_sum[tid], ts);
        atomicAdd(&g_sq [tid], tq);
    }
    __threadfence();
    if (tid == 0) {
        int old = atomicAdd(&g_done, 1);
        lastFlag = (old == (int)gridDim.x - 1);
    }
    __syncthreads();
    if (lastFlag) {
        if (tid < 128) {
            float sv = *((volatile float*)&g_sum[tid]);
            float qv = *((volatile float*)&g_sq [tid]);
            float mean = sv * (1.f / N_ACT);
            float var  = qv * (1.f / N_ACT) - mean * mean;
            float istd = rsqrtf(var + EPSV);
            float sc = gamma[tid] * istd;
            g_scale[tid] = sc;
            g_shift[tid] = beta[tid] - mean * sc;
            g_sum[tid] = 0.f;
            g_sq [tid] = 0.f;
        }
        __threadfence();
        if (tid == 0) g_done = 0;
    }
}

// ---------------- layer-2: stats + finalize + BN/residual/ReLU in ONE kernel -
// All blocks are co-resident (304 blocks, 256 thr, ~1KB smem), so a device-side
// flag spin after the stats reduction is deadlock-free.
__global__ void __launch_bounds__(256) statsfinal_k(
    const float* __restrict__ y, const float* __restrict__ x,
    const float* __restrict__ gamma, const float* __restrict__ beta,
    float* __restrict__ outp)
{
    __shared__ float ssum[8][32][4];
    __shared__ float ssq [8][32][4];
    __shared__ int lastFlag;

    int tid = threadIdx.x;
    int wid = tid >> 5;
    int c4  = tid & 31;

    float4 s = make_float4(0.f, 0.f, 0.f, 0.f);
    float4 q = make_float4(0.f, 0.f, 0.f, 0.f);
#pragma unroll 4
    for (int r = blockIdx.x * 8 + wid; r < N_ACT; r += gridDim.x * 8) {
        float4 v = *(const float4*)&y[(long)r * Cc + c4 * 4];
        s.x += v.x; s.y += v.y; s.z += v.z; s.w += v.w;
        q.x += v.x * v.x; q.y += v.y * v.y; q.z += v.z * v.z; q.w += v.w * v.w;
    }
    ssum[wid][c4][0] = s.x; ssum[wid][c4][1] = s.y;
    ssum[wid][c4][2] = s.z; ssum[wid][c4][3] = s.w;
    ssq [wid][c4][0] = q.x; ssq [wid][c4][1] = q.y;
    ssq [wid][c4][2] = q.z; ssq [wid][c4][3] = q.w;
    __syncthreads();

    if (tid < 128) {
        int cg = tid >> 2, j = tid & 3;
        float ts = 0.f, tq = 0.f;
#pragma unroll
        for (int w = 0; w < 8; w++) { ts += ssum[w][cg][j]; tq += ssq[w][cg][j]; }
        atomicAdd(&g_sum[tid], ts);
        atomicAdd(&g_sq [tid], tq);
    }
    __threadfence();
    if (tid == 0) {
        int old = atomicAdd(&g_done, 1);
        lastFlag = (old == (int)gridDim.x - 1);
    }
    __syncthreads();
    if (lastFlag) {
        if (tid < 128) {
            float sv = *((volatile float*)&g_sum[tid]);
            float qv = *((volatile float*)&g_sq [tid]);
            float mean = sv * (1.f / N_ACT);
            float var  = qv * (1.f / N_ACT) - mean * mean;
            float istd = rsqrtf(var + EPSV);
            float sc = gamma[tid] * istd;
            g_scale[tid] = sc;
            g_shift[tid] = beta[tid] - mean * sc;
            g_sum[tid] = 0.f;
            g_sq [tid] = 0.f;
        }
        if (tid >= 128 && tid < 128 + NTAPS) g_cnt[tid - 128] = 0;
        __threadfence();
        if (tid == 0) atomicExch(&g_flag, 1);
    }

    // spin until scale/shift published (all blocks co-resident -> safe)
    if (tid == 0) { while (atomicAdd(&g_flag, 0) == 0) {} }
    __syncthreads();

    // apply BN + residual + ReLU over this block's strided float4 range
    int total = N_ACT * Cc / 4;
    for (int i = blockIdx.x * 256 + tid; i < total; i += gridDim.x * 256) {
        int cc = (i & 31) * 4;
        float4 v  = ((const float4*)y)[i];
        float4 xv = ((const float4*)x)[i];
        float4 sc = *(const float4*)&g_scale[cc];
        float4 sh = *(const float4*)&g_shift[cc];
        float4 o;
        o.x = fmaxf(v.x * sc.x + sh.x + xv.x, 0.f);
        o.y = fmaxf(v.y * sc.y + sh.y + xv.y, 0.f);
        o.z = fmaxf(v.z * sc.z + sh.z + xv.z, 0.f);
        o.w = fmaxf(v.w * sc.w + sh.w + xv.w, 0.f);
        ((float4*)outp)[i] = o;
    }

    // reset flags for deterministic graph replay
    if (tid == 0) {
        int old = atomicAdd(&g_done2, 1);
        if (old == (int)gridDim.x - 1) {
            g_done  = 0;
            g_done2 = 0;
            g_flag  = 0;
            __threadfence();
        }
    }
}

// ---------------- launch ------------------------------------------------------
extern "C" void kernel_launch(void* const* d_in, const int* in_sizes, int n_in,
                              void* d_out, int out_size)
{
    const float* x   = (const float*)d_in[0];
    const int*   nbr = (const int*)  d_in[1];
    const float* W1  = (const float*)d_in[2];
    const float* g1  = (const float*)d_in[3];
    const float* b1  = (const float*)d_in[4];
    const float* W2  = (const float*)d_in[5];
    const float* g2  = (const float*)d_in[6];
    const float* b2  = (const float*)d_in[7];
    float* out = (float*)d_out;

    float* buf1; cudaGetSymbolAddress((void**)&buf1, g_buf1);
    float* buf2; cudaGetSymbolAddress((void**)&buf2, g_buf2);

    const int SMEM = (WP_FLOATS + 2 * AS_STAGE) * 4 + 256 * 4 + 2 * 128 * 4;
    cudaFuncSetAttribute(conv_mma_k<true,  false, true >, cudaFuncAttributeMaxDynamicSharedMemorySize, SMEM);
    cudaFuncSetAttribute(conv_mma_k<false, false, false>, cudaFuncAttributeMaxDynamicSharedMemorySize, SMEM);
    cudaFuncSetAttribute(conv_mma_k<true,  true,  false>, cudaFuncAttributeMaxDynamicSharedMemorySize, SMEM);
    cudaFuncSetAttribute(conv_mma_k<false, true,  false>, cudaFuncAttributeMaxDynamicSharedMemorySize, SMEM);

    // ---- layer 1 (rulebook built inside the center conv prologue) ----
    conv_mma_k<true,  false, true ><<<304, 256, SMEM>>>(x, W1 + 4 * Cc * Cc, buf1, nbr);
    conv_mma_k<false, false, false><<<dim3(38, NTAPS), 256, SMEM>>>(x, W1, buf1, nullptr);
    stats_k<<<304, 256>>>(buf1, g1, b1);

    // ---- layer 2 (BN+ReLU of layer 1 fused into A loads) ----
    conv_mma_k<true,  true,  false><<<304, 256, SMEM>>>(buf1, W2 + 4 * Cc * Cc, buf2, nullptr);
    conv_mma_k<false, true,  false><<<dim3(38, NTAPS), 256, SMEM>>>(buf1, W2, buf2, nullptr);
    statsfinal_k<<<304, 256>>>(buf2, x, g2, b2, out);
}

// round 14
// speedup vs baseline: 1.0735x; 1.0735x over previous
#include <cuda_runtime.h>
#include <cstdint>

#define N_ACT 300000
#define Cc 128
#define NTAPS 8
#define EPSV 1e-4f

// ---------------- scratch (device globals; zero-initialized at load) --------
__device__ float g_buf1[N_ACT * Cc];
__device__ float g_buf2[N_ACT * Cc];
__device__ int   g_pin [NTAPS * N_ACT];
__device__ int   g_pout[NTAPS * N_ACT];
__device__ int   g_cnt [NTAPS];          // self-reset by layer-2 stats
__device__ float g_sum[Cc], g_sq[Cc];    // self-reset by stats
__device__ float g_scale[Cc], g_shift[Cc];
__device__ int   g_done;                 // self-reset by stats

// ---------------- helpers ----------------------------------------------------
__device__ __forceinline__ uint32_t tf32u(float x) {
    uint32_t y;
    asm("cvt.rna.tf32.f32 %0, %1;" : "=r"(y) : "f"(x));
    return y;
}
__device__ __forceinline__ float tf32r(float x) { return __uint_as_float(tf32u(x)); }

__device__ __forceinline__ void mma8(float* d, const uint32_t* a, const uint32_t* b) {
    asm volatile(
        "mma.sync.aligned.m16n8k8.row.col.f32.tf32.tf32.f32 "
        "{%0,%1,%2,%3}, {%4,%5,%6,%7}, {%8,%9}, {%0,%1,%2,%3};"
        : "+f"(d[0]), "+f"(d[1]), "+f"(d[2]), "+f"(d[3])
        : "r"(a[0]), "r"(a[1]), "r"(a[2]), "r"(a[3]), "r"(b[0]), "r"(b[1]));
}

__device__ __forceinline__ void ldsm_x4(uint32_t* r, uint32_t addr) {
    asm volatile("ldmatrix.sync.aligned.m8n8.x4.shared.b16 {%0,%1,%2,%3}, [%4];"
                 : "=r"(r[0]), "=r"(r[1]), "=r"(r[2]), "=r"(r[3]) : "r"(addr));
}

__device__ __forceinline__ void red_add2(float* p, float a, float b) {
    asm volatile("red.relaxed.gpu.global.add.v2.f32 [%0], {%1, %2};"
                 :: "l"(p), "f"(a), "f"(b) : "memory");
}

__device__ __forceinline__ uint32_t smem_u32(const void* p) {
    uint32_t a;
    asm("{ .reg .u64 t; cvta.to.shared.u64 t, %1; cvt.u32.u64 %0, t; }" : "=r"(a) : "l"(p));
    return a;
}

// SMEM geometry
#define WP_STRIDE 132                        // float2 units per (s,tig) row
#define WP_FLOATS (16 * 4 * WP_STRIDE * 2)   // 16896 floats
#define AS_STRIDE 36                         // floats per A row (144B)
#define AS_STAGE  (128 * AS_STRIDE)

// ---------------- rulebook slice builder (runs inside layer-1 center conv) ---
__device__ void build_rulebook_slice(const int* __restrict__ nbr, int tid,
                                     int bx, int nBlocks) {
    __shared__ int scnt[NTAPS], sbase[NTAPS];
    int rowsPer = (N_ACT + nBlocks - 1) / nBlocks;
    int begin = bx * rowsPer;
    int end = begin + rowsPer;
    if (end > N_ACT) end = N_ACT;
    for (int base = begin; base < end; base += 256) {
        if (tid < NTAPS) scnt[tid] = 0;
        __syncthreads();
        int i = base + tid;
        bool act = (i < end);
        int idxv[NTAPS], lpos[NTAPS];
#pragma unroll
        for (int k = 0; k < 9; k++) {
            if (k == 4) continue;
            int t = (k < 4) ? k : k - 1;
            int idx = act ? nbr[i * 9 + k] : -1;
            idxv[t] = idx;
            lpos[t] = (idx >= 0) ? atomicAdd(&scnt[t], 1) : -1;
        }
        __syncthreads();
        if (tid < NTAPS) sbase[tid] = atomicAdd(&g_cnt[tid], scnt[tid]);
        __syncthreads();
#pragma unroll
        for (int t = 0; t < NTAPS; t++) {
            if (lpos[t] >= 0) {
                int pos = sbase[t] + lpos[t];
                g_pin [t * N_ACT + pos] = idxv[t];
                g_pout[t * N_ACT + pos] = i;
            }
        }
    }
}

// ---------------- tf32 mma.sync GEMM, cross-tile cp.async pipeline -----------
// CTA tile 128x128, K=128 in 4 chunks of 32; 8 warps (4m x 2n), 2x8 frags.
// A fragments via ldmatrix.x4 (M0..M3 = rows {0-7,8-15} x cols {k0,k0+4}).
template <bool CENTER, bool BN, bool RB>
__global__ void __launch_bounds__(256, 2) conv_mma_k(
    const float* __restrict__ in, const float* __restrict__ W,
    float* __restrict__ out, const int* __restrict__ nbr)
{
    extern __shared__ float smem[];
    float2* Wp = (float2*)smem;                        // [16][4][WP_STRIDE]
    float*  As = smem + WP_FLOATS;                     // 2 stages x 128*36
    int*    rin  = (int*)(As + 2 * AS_STAGE);          // [2][128]
    float*  ssc  = (float*)(rin + 256);
    float*  ssh  = ssc + 128;

    const uint32_t asu = smem_u32(As);

    int tid = threadIdx.x;
    int wid = tid >> 5, lane = tid & 31;
    int wm = wid >> 1, wn = wid & 1;
    int grp = lane >> 2, tig = lane & 3;

    // per-lane ldmatrix row offset: lane i -> matrix i>>3, row i&7
    int mm = lane >> 3, rr = lane & 7;
    const uint32_t a_off =
        (uint32_t)((wm * 32 + rr + (mm & 1) * 8) * 144 + (mm >> 1) * 16);

    const float* Wk;
    const int *pin = nullptr, *pout = nullptr;
    int cnt;
    if (CENTER) {
        Wk = W;
        cnt = N_ACT;
    } else {
        int tap = blockIdx.y;
        cnt = g_cnt[tap];
        int kk = (tap < 4) ? tap : tap + 1;
        Wk = W + (long)kk * Cc * Cc;
        pin  = g_pin  + (long)tap * N_ACT;
        pout = g_pout + (long)tap * N_ACT;
    }

    // Stage W[k][n] -> paired float2 layout (tf32-rounded), once per CTA.
    for (int i = tid; i < 128 * 32; i += 256) {
        int k = i >> 5, n4 = (i & 31) * 4;
        float4 v = *(const float4*)&Wk[k * Cc + n4];
        int s = k >> 3, r = k & 7, t = r & 3, half = r >> 2;
        float* d = smem + (((s * 4 + t) * WP_STRIDE + n4) * 2 + half);
        d[0] = tf32r(v.x); d[2] = tf32r(v.y); d[4] = tf32r(v.z); d[6] = tf32r(v.w);
    }
    if (BN && tid < 128) { ssc[tid] = g_scale[tid]; ssh[tid] = g_shift[tid]; }

    int numTiles = (cnt + 127) >> 7;
    int step = gridDim.x;
    int tile0 = blockIdx.x;

    auto issue = [&](int tileI, int kc, int stage, const int* rbuf, bool valid) {
        if (valid) {
            uint32_t sbase = asu + (uint32_t)stage * (AS_STAGE * 4);
            int m0 = tileI << 7;
#pragma unroll
            for (int l = 0; l < 4; l++) {
                int idx = tid + l * 256;          // 0..1023 16B-chunks
                int rloc = idx >> 3, c16 = idx & 7;
                int rg;
                if (CENTER) { int m = m0 + rloc; rg = (m < N_ACT) ? m : -1; }
                else        rg = rbuf[rloc];
                const float* src = in + (long)(rg < 0 ? 0 : rg) * Cc + kc * 32 + c16 * 4;
                uint32_t dst = sbase + (uint32_t)(rloc * 144 + c16 * 16);
                int sz = (rg >= 0) ? 16 : 0;
                asm volatile("cp.async.cg.shared.global [%0], [%1], 16, %2;"
                             :: "r"(dst), "l"(src), "r"(sz));
            }
        }
        asm volatile("cp.async.commit_group;" ::: "memory");
    };

    if (!CENTER && tid < 128) {
        int m = (tile0 << 7) + tid;
        rin[tid] = (tile0 < numTiles && m < cnt) ? pin[m] : -1;
    }
    __syncthreads();
    issue(tile0, 0, 0, rin, tile0 < numTiles);

    // rulebook prologue (layer-1 center only) — overlaps with chunk-0 loads
    if (RB) build_rulebook_slice(nbr, tid, blockIdx.x, gridDim.x);

    int it = 0;
    for (int tile = tile0; tile < numTiles; tile += step, it++) {
        int cbuf = it & 1, nbuf = cbuf ^ 1;
        int nextTile = tile + step;
        bool nextValid = nextTile < numTiles;

        if (!CENTER && tid < 128) {
            int m = (nextTile << 7) + tid;
            rin[nbuf * 128 + tid] = (nextValid && m < cnt) ? pin[m] : -1;
        }

        int ro[2][2];
        if (!CENTER) {
#pragma unroll
            for (int mt = 0; mt < 2; mt++) {
                int r0 = (tile << 7) + wm * 32 + mt * 16 + grp;
                ro[mt][0] = (r0     < cnt) ? pout[r0]     : -1;
                ro[mt][1] = (r0 + 8 < cnt) ? pout[r0 + 8] : -1;
            }
        }

        float acc[2][8][4];
#pragma unroll
        for (int a = 0; a < 2; a++)
#pragma unroll
            for (int b = 0; b < 8; b++)
#pragma unroll
                for (int c = 0; c < 4; c++) acc[a][b][c] = 0.f;

#pragma unroll
        for (int kc = 0; kc < 4; kc++) {
            if (kc < 3) issue(tile, kc + 1, (kc + 1) & 1, rin + cbuf * 128, true);
            else        issue(nextTile, 0, 0, rin + nbuf * 128, nextValid);

            asm volatile("cp.async.wait_group 1;" ::: "memory");
            __syncthreads();

            uint32_t abase = asu + (uint32_t)(kc & 1) * (AS_STAGE * 4) + a_off;

#pragma unroll
            for (int ks = 0; ks < 4; ks++) {
                int k0 = ks * 8;
                int s  = kc * 4 + ks;
                int ka = kc * 32 + k0 + tig;
                int kb = ka + 4;
                float sca = 0.f, sha = 0.f, scb = 0.f, shb = 0.f;
                if (BN) { sca = ssc[ka]; sha = ssh[ka]; scb = ssc[kb]; shb = ssh[kb]; }

                uint32_t afr[2][4], bfr[8][2];
#pragma unroll
                for (int mt = 0; mt < 2; mt++) {
                    ldsm_x4(afr[mt], abase + (uint32_t)(k0 * 4 + mt * 2304));
                    if (BN) {
                        float e0 = fmaxf(__uint_as_float(afr[mt][0]) * sca + sha, 0.f);
                        float e1 = fmaxf(__uint_as_float(afr[mt][1]) * sca + sha, 0.f);
                        float e2 = fmaxf(__uint_as_float(afr[mt][2]) * scb + shb, 0.f);
                        float e3 = fmaxf(__uint_as_float(afr[mt][3]) * scb + shb, 0.f);
                        afr[mt][0] = __float_as_uint(e0);
                        afr[mt][1] = __float_as_uint(e1);
                        afr[mt][2] = __float_as_uint(e2);
                        afr[mt][3] = __float_as_uint(e3);
                    }
                }
                const float2* wps = Wp + (s * 4 + tig) * WP_STRIDE;
#pragma unroll
                for (int nt = 0; nt < 8; nt++) {
                    int col = wn * 64 + nt * 8 + grp;
                    float2 p = wps[col];
                    bfr[nt][0] = __float_as_uint(p.x);
                    bfr[nt][1] = __float_as_uint(p.y);
                }
#pragma unroll
                for (int mt = 0; mt < 2; mt++)
#pragma unroll
                    for (int nt = 0; nt < 8; nt++)
                        mma8(acc[mt][nt], afr[mt], bfr[nt]);
            }
            __syncthreads();
        }

        int m0 = tile << 7;
#pragma unroll
        for (int mt = 0; mt < 2; mt++) {
            if (CENTER) {
                int m0r = m0 + wm * 32 + mt * 16 + grp;
                int m1r = m0r + 8;
#pragma unroll
                for (int nt = 0; nt < 8; nt++) {
                    int col = wn * 64 + nt * 8 + tig * 2;
                    if (m0r < N_ACT)
                        *(float2*)&out[(long)m0r * Cc + col] =
                            make_float2(acc[mt][nt][0], acc[mt][nt][1]);
                    if (m1r < N_ACT)
                        *(float2*)&out[(long)m1r * Cc + col] =
                            make_float2(acc[mt][nt][2], acc[mt][nt][3]);
                }
            } else {
                int ro0 = ro[mt][0], ro1 = ro[mt][1];
#pragma unroll
                for (int nt = 0; nt < 8; nt++) {
                    int col = wn * 64 + nt * 8 + tig * 2;
                    if (ro0 >= 0)
                        red_add2(&out[(long)ro0 * Cc + col], acc[mt][nt][0], acc[mt][nt][1]);
                    if (ro1 >= 0)
                        red_add2(&out[(long)ro1 * Cc + col], acc[mt][nt][2], acc[mt][nt][3]);
                }
            }
        }
    }
    asm volatile("cp.async.wait_group 0;" ::: "memory");
}

// ---------------- per-channel stats + fused finalize (last block) ------------
// Last block also re-zeros g_sum/g_sq/g_done; if RESETCNT, zeroes g_cnt too
// (safe: runs after the last consumer of the rulebook in this call).
template <bool RESETCNT>
__global__ void __launch_bounds__(256) stats_k(
    const float* __restrict__ y,
    const float* __restrict__ gamma, const float* __restrict__ beta)
{
    __shared__ float ssum[8][32][4];
    __shared__ float ssq [8][32][4];
    __shared__ int lastFlag;

    int tid = threadIdx.x;
    int wid = tid >> 5;
    int c4  = tid & 31;

    float4 s = make_float4(0.f, 0.f, 0.f, 0.f);
    float4 q = make_float4(0.f, 0.f, 0.f, 0.f);
#pragma unroll 4
    for (int r = blockIdx.x * 8 + wid; r < N_ACT; r += gridDim.x * 8) {
        float4 v = *(const float4*)&y[(long)r * Cc + c4 * 4];
        s.x += v.x; s.y += v.y; s.z += v.z; s.w += v.w;
        q.x += v.x * v.x; q.y += v.y * v.y; q.z += v.z * v.z; q.w += v.w * v.w;
    }
    ssum[wid][c4][0] = s.x; ssum[wid][c4][1] = s.y;
    ssum[wid][c4][2] = s.z; ssum[wid][c4][3] = s.w;
    ssq [wid][c4][0] = q.x; ssq [wid][c4][1] = q.y;
    ssq [wid][c4][2] = q.z; ssq [wid][c4][3] = q.w;
    __syncthreads();

    if (tid < 128) {
        int cg = tid >> 2, j = tid & 3;
        float ts = 0.f, tq = 0.f;
#pragma unroll
        for (int w = 0; w < 8; w++) { ts += ssum[w][cg][j]; tq += ssq[w][cg][j]; }
        atomicAdd(&g_sum[tid], ts);
        atomicAdd(&g_sq [tid], tq);
    }
    __threadfence();
    if (tid == 0) {
        int old = atomicAdd(&g_done, 1);
        lastFlag = (old == (int)gridDim.x - 1);
    }
    __syncthreads();
    if (lastFlag) {
        if (tid < 128) {
            float sv = *((volatile float*)&g_sum[tid]);
            float qv = *((volatile float*)&g_sq [tid]);
            float mean = sv * (1.f / N_ACT);
            float var  = qv * (1.f / N_ACT) - mean * mean;
            float istd = rsqrtf(var + EPSV);
            float sc = gamma[tid] * istd;
            g_scale[tid] = sc;
            g_shift[tid] = beta[tid] - mean * sc;
            g_sum[tid] = 0.f;
            g_sq [tid] = 0.f;
        }
        if (RESETCNT && tid >= 128 && tid < 128 + NTAPS)
            g_cnt[tid - 128] = 0;
        __threadfence();
        if (tid == 0) g_done = 0;
    }
}

__global__ __launch_bounds__(256) void final_k(
    const float* __restrict__ y, const float* __restrict__ x, float* __restrict__ outp)
{
    int i = blockIdx.x * blockDim.x + threadIdx.x;
    if (i >= N_ACT * Cc / 4) return;
    int c4 = (i & 31) * 4;
    float4 v  = ((const float4*)y)[i];
    float4 xv = ((const float4*)x)[i];
    float4 sc = *(const float4*)&g_scale[c4];
    float4 sh = *(const float4*)&g_shift[c4];
    float4 o;
    o.x = fmaxf(v.x * sc.x + sh.x + xv.x, 0.f);
    o.y = fmaxf(v.y * sc.y + sh.y + xv.y, 0.f);
    o.z = fmaxf(v.z * sc.z + sh.z + xv.z, 0.f);
    o.w = fmaxf(v.w * sc.w + sh.w + xv.w, 0.f);
    ((float4*)outp)[i] = o;
}

// ---------------- launch ------------------------------------------------------
extern "C" void kernel_launch(void* const* d_in, const int* in_sizes, int n_in,
                              void* d_out, int out_size)
{
    const float* x   = (const float*)d_in[0];
    const int*   nbr = (const int*)  d_in[1];
    const float* W1  = (const float*)d_in[2];
    const float* g1  = (const float*)d_in[3];
    const float* b1  = (const float*)d_in[4];
    const float* W2  = (const float*)d_in[5];
    const float* g2  = (const float*)d_in[6];
    const float* b2  = (const float*)d_in[7];
    float* out = (float*)d_out;

    float* buf1; cudaGetSymbolAddress((void**)&buf1, g_buf1);
    float* buf2; cudaGetSymbolAddress((void**)&buf2, g_buf2);

    const int SMEM = (WP_FLOATS + 2 * AS_STAGE) * 4 + 256 * 4 + 2 * 128 * 4;
    cudaFuncSetAttribute(conv_mma_k<true,  false, true >, cudaFuncAttributeMaxDynamicSharedMemorySize, SMEM);
    cudaFuncSetAttribute(conv_mma_k<false, false, false>, cudaFuncAttributeMaxDynamicSharedMemorySize, SMEM);
    cudaFuncSetAttribute(conv_mma_k<true,  true,  false>, cudaFuncAttributeMaxDynamicSharedMemorySize, SMEM);
    cudaFuncSetAttribute(conv_mma_k<false, true,  false>, cudaFuncAttributeMaxDynamicSharedMemorySize, SMEM);

    const int ewBlocks = (N_ACT * Cc / 4 + 255) / 256;

    // ---- layer 1 (rulebook built inside the center conv prologue) ----
    conv_mma_k<true,  false, true ><<<304, 256, SMEM>>>(x, W1 + 4 * Cc * Cc, buf1, nbr);
    conv_mma_k<false, false, false><<<dim3(38, NTAPS), 256, SMEM>>>(x, W1, buf1, nullptr);
    stats_k<false><<<304, 256>>>(buf1, g1, b1);

    // ---- layer 2 (BN+ReLU of layer 1 fused into A loads) ----
    conv_mma_k<true,  true,  false><<<304, 256, SMEM>>>(buf1, W2 + 4 * Cc * Cc, buf2, nullptr);
    conv_mma_k<false, true,  false><<<dim3(38, NTAPS), 256, SMEM>>>(buf1, W2, buf2, nullptr);
    stats_k<true><<<304, 256>>>(buf2, g2, b2);
    final_k<<<ewBlocks, 256>>>(buf2, x, out);
}

// round 15
// speedup vs baseline: 1.1074x; 1.0316x over previous
#include <cuda_runtime.h>
#include <cstdint>

#define N_ACT 300000
#define Cc 128
#define NTAPS 8
#define EPSV 1e-4f

// ---------------- scratch (device globals; zero-initialized at load) --------
__device__ float g_buf1[N_ACT * Cc];
__device__ float g_buf2[N_ACT * Cc];
__device__ int   g_pin [NTAPS * N_ACT];
__device__ int   g_pout[NTAPS * N_ACT];
__device__ int   g_cnt [NTAPS];          // self-reset by layer-2 stats
__device__ float g_sum[Cc], g_sq[Cc];    // self-reset by stats
__device__ float g_scale[Cc], g_shift[Cc];
__device__ int   g_done;                 // self-reset by stats

// ---------------- helpers ----------------------------------------------------
__device__ __forceinline__ void pdl_wait()    { asm volatile("griddepcontrol.wait;" ::: "memory"); }
__device__ __forceinline__ void pdl_trigger() { asm volatile("griddepcontrol.launch_dependents;"); }

__device__ __forceinline__ uint32_t tf32u(float x) {
    uint32_t y;
    asm("cvt.rna.tf32.f32 %0, %1;" : "=r"(y) : "f"(x));
    return y;
}
__device__ __forceinline__ float tf32r(float x) { return __uint_as_float(tf32u(x)); }

__device__ __forceinline__ void mma8(float* d, const uint32_t* a, const uint32_t* b) {
    asm volatile(
        "mma.sync.aligned.m16n8k8.row.col.f32.tf32.tf32.f32 "
        "{%0,%1,%2,%3}, {%4,%5,%6,%7}, {%8,%9}, {%0,%1,%2,%3};"
        : "+f"(d[0]), "+f"(d[1]), "+f"(d[2]), "+f"(d[3])
        : "r"(a[0]), "r"(a[1]), "r"(a[2]), "r"(a[3]), "r"(b[0]), "r"(b[1]));
}

__device__ __forceinline__ void ldsm_x4(uint32_t* r, uint32_t addr) {
    asm volatile("ldmatrix.sync.aligned.m8n8.x4.shared.b16 {%0,%1,%2,%3}, [%4];"
                 : "=r"(r[0]), "=r"(r[1]), "=r"(r[2]), "=r"(r[3]) : "r"(addr));
}

__device__ __forceinline__ void red_add2(float* p, float a, float b) {
    asm volatile("red.relaxed.gpu.global.add.v2.f32 [%0], {%1, %2};"
                 :: "l"(p), "f"(a), "f"(b) : "memory");
}

__device__ __forceinline__ uint32_t smem_u32(const void* p) {
    uint32_t a;
    asm("{ .reg .u64 t; cvta.to.shared.u64 t, %1; cvt.u32.u64 %0, t; }" : "=r"(a) : "l"(p));
    return a;
}

// SMEM geometry
#define WP_STRIDE 132                        // float2 units per (s,tig) row
#define WP_FLOATS (16 * 4 * WP_STRIDE * 2)   // 16896 floats
#define AS_STRIDE 36                         // floats per A row (144B)
#define AS_STAGE  (128 * AS_STRIDE)

// ---------------- rulebook slice builder (runs inside layer-1 center conv) ---
__device__ void build_rulebook_slice(const int* __restrict__ nbr, int tid,
                                     int bx, int nBlocks) {
    __shared__ int scnt[NTAPS], sbase[NTAPS];
    int rowsPer = (N_ACT + nBlocks - 1) / nBlocks;
    int begin = bx * rowsPer;
    int end = begin + rowsPer;
    if (end > N_ACT) end = N_ACT;
    for (int base = begin; base < end; base += 256) {
        if (tid < NTAPS) scnt[tid] = 0;
        __syncthreads();
        int i = base + tid;
        bool act = (i < end);
        int idxv[NTAPS], lpos[NTAPS];
#pragma unroll
        for (int k = 0; k < 9; k++) {
            if (k == 4) continue;
            int t = (k < 4) ? k : k - 1;
            int idx = act ? nbr[i * 9 + k] : -1;
            idxv[t] = idx;
            lpos[t] = (idx >= 0) ? atomicAdd(&scnt[t], 1) : -1;
        }
        __syncthreads();
        if (tid < NTAPS) sbase[tid] = atomicAdd(&g_cnt[tid], scnt[tid]);
        __syncthreads();
#pragma unroll
        for (int t = 0; t < NTAPS; t++) {
            if (lpos[t] >= 0) {
                int pos = sbase[t] + lpos[t];
                g_pin [t * N_ACT + pos] = idxv[t];
                g_pout[t * N_ACT + pos] = i;
            }
        }
    }
}

// ---------------- tf32 mma.sync GEMM, cross-tile cp.async pipeline -----------
// CTA tile 128x128, K=128 in 4 chunks of 32; 8 warps (4m x 2n), 2x8 frags.
// A fragments via ldmatrix.x4. W staging runs BEFORE the PDL wait (prologue
// reads only the harness input W); all predecessor-produced state is read
// after pdl_wait().
template <bool CENTER, bool BN, bool RB>
__global__ void __launch_bounds__(256, 2) conv_mma_k(
    const float* __restrict__ in, const float* __restrict__ W,
    float* __restrict__ out, const int* __restrict__ nbr)
{
    extern __shared__ float smem[];
    float2* Wp = (float2*)smem;                        // [16][4][WP_STRIDE]
    float*  As = smem + WP_FLOATS;                     // 2 stages x 128*36
    int*    rin  = (int*)(As + 2 * AS_STAGE);          // [2][128]
    float*  ssc  = (float*)(rin + 256);
    float*  ssh  = ssc + 128;

    const uint32_t asu = smem_u32(As);

    int tid = threadIdx.x;
    int wid = tid >> 5, lane = tid & 31;
    int wm = wid >> 1, wn = wid & 1;
    int grp = lane >> 2, tig = lane & 3;

    // per-lane ldmatrix row offset: lane i -> matrix i>>3, row i&7
    int mm = lane >> 3, rr = lane & 7;
    const uint32_t a_off =
        (uint32_t)((wm * 32 + rr + (mm & 1) * 8) * 144 + (mm >> 1) * 16);

    // W pointer: blockIdx math only — no dependent reads
    const float* Wk = CENTER ? W
                             : W + (long)((blockIdx.y < 4) ? blockIdx.y : blockIdx.y + 1) * Cc * Cc;

    // ---- prologue (independent of predecessor): stage W -> smem -------------
    for (int i = tid; i < 128 * 32; i += 256) {
        int k = i >> 5, n4 = (i & 31) * 4;
        float4 v = *(const float4*)&Wk[k * Cc + n4];
        int s = k >> 3, r = k & 7, t = r & 3, half = r >> 2;
        float* d = smem + (((s * 4 + t) * WP_STRIDE + n4) * 2 + half);
        d[0] = tf32r(v.x); d[2] = tf32r(v.y); d[4] = tf32r(v.z); d[6] = tf32r(v.w);
    }

    // ---- wait for predecessor; let successor launch ------------------------
    pdl_wait();
    pdl_trigger();

    const int *pin = nullptr, *pout = nullptr;
    int cnt;
    if (CENTER) {
        cnt = N_ACT;
    } else {
        int tap = blockIdx.y;
        cnt = g_cnt[tap];
        pin  = g_pin  + (long)tap * N_ACT;
        pout = g_pout + (long)tap * N_ACT;
    }
    if (BN && tid < 128) { ssc[tid] = g_scale[tid]; ssh[tid] = g_shift[tid]; }

    int numTiles = (cnt + 127) >> 7;
    int step = gridDim.x;
    int tile0 = blockIdx.x;

    auto issue = [&](int tileI, int kc, int stage, const int* rbuf, bool valid) {
        if (valid) {
            uint32_t sbase = asu + (uint32_t)stage * (AS_STAGE * 4);
            int m0 = tileI << 7;
#pragma unroll
            for (int l = 0; l < 4; l++) {
                int idx = tid + l * 256;          // 0..1023 16B-chunks
                int rloc = idx >> 3, c16 = idx & 7;
                int rg;
                if (CENTER) { int m = m0 + rloc; rg = (m < N_ACT) ? m : -1; }
                else        rg = rbuf[rloc];
                const float* src = in + (long)(rg < 0 ? 0 : rg) * Cc + kc * 32 + c16 * 4;
                uint32_t dst = sbase + (uint32_t)(rloc * 144 + c16 * 16);
                int sz = (rg >= 0) ? 16 : 0;
                asm volatile("cp.async.cg.shared.global [%0], [%1], 16, %2;"
                             :: "r"(dst), "l"(src), "r"(sz));
            }
        }
        asm volatile("cp.async.commit_group;" ::: "memory");
    };

    if (!CENTER && tid < 128) {
        int m = (tile0 << 7) + tid;
        rin[tid] = (tile0 < numTiles && m < cnt) ? pin[m] : -1;
    }
    __syncthreads();   // also covers W staging
    issue(tile0, 0, 0, rin, tile0 < numTiles);

    // rulebook prologue (layer-1 center only) — overlaps with chunk-0 loads
    if (RB) build_rulebook_slice(nbr, tid, blockIdx.x, gridDim.x);

    int it = 0;
    for (int tile = tile0; tile < numTiles; tile += step, it++) {
        int cbuf = it & 1, nbuf = cbuf ^ 1;
        int nextTile = tile + step;
        bool nextValid = nextTile < numTiles;

        if (!CENTER && tid < 128) {
            int m = (nextTile << 7) + tid;
            rin[nbuf * 128 + tid] = (nextValid && m < cnt) ? pin[m] : -1;
        }

        int ro[2][2];
        if (!CENTER) {
#pragma unroll
            for (int mt = 0; mt < 2; mt++) {
                int r0 = (tile << 7) + wm * 32 + mt * 16 + grp;
                ro[mt][0] = (r0     < cnt) ? pout[r0]     : -1;
                ro[mt][1] = (r0 + 8 < cnt) ? pout[r0 + 8] : -1;
            }
        }

        float acc[2][8][4];
#pragma unroll
        for (int a = 0; a < 2; a++)
#pragma unroll
            for (int b = 0; b < 8; b++)
#pragma unroll
                for (int c = 0; c < 4; c++) acc[a][b][c] = 0.f;

#pragma unroll
        for (int kc = 0; kc < 4; kc++) {
            if (kc < 3) issue(tile, kc + 1, (kc + 1) & 1, rin + cbuf * 128, true);
            else        issue(nextTile, 0, 0, rin + nbuf * 128, nextValid);

            asm volatile("cp.async.wait_group 1;" ::: "memory");
            __syncthreads();

            uint32_t abase = asu + (uint32_t)(kc & 1) * (AS_STAGE * 4) + a_off;

#pragma unroll
            for (int ks = 0; ks < 4; ks++) {
                int k0 = ks * 8;
                int s  = kc * 4 + ks;
                int ka = kc * 32 + k0 + tig;
                int kb = ka + 4;
                float sca = 0.f, sha = 0.f, scb = 0.f, shb = 0.f;
                if (BN) { sca = ssc[ka]; sha = ssh[ka]; scb = ssc[kb]; shb = ssh[kb]; }

                uint32_t afr[2][4], bfr[8][2];
#pragma unroll
                for (int mt = 0; mt < 2; mt++) {
                    ldsm_x4(afr[mt], abase + (uint32_t)(k0 * 4 + mt * 2304));
                    if (BN) {
                        float e0 = fmaxf(__uint_as_float(afr[mt][0]) * sca + sha, 0.f);
                        float e1 = fmaxf(__uint_as_float(afr[mt][1]) * sca + sha, 0.f);
                        float e2 = fmaxf(__uint_as_float(afr[mt][2]) * scb + shb, 0.f);
                        float e3 = fmaxf(__uint_as_float(afr[mt][3]) * scb + shb, 0.f);
                        afr[mt][0] = __float_as_uint(e0);
                        afr[mt][1] = __float_as_uint(e1);
                        afr[mt][2] = __float_as_uint(e2);
                        afr[mt][3] = __float_as_uint(e3);
                    }
                }
                const float2* wps = Wp + (s * 4 + tig) * WP_STRIDE;
#pragma unroll
                for (int nt = 0; nt < 8; nt++) {
                    int col = wn * 64 + nt * 8 + grp;
                    float2 p = wps[col];
                    bfr[nt][0] = __float_as_uint(p.x);
                    bfr[nt][1] = __float_as_uint(p.y);
                }
#pragma unroll
                for (int mt = 0; mt < 2; mt++)
#pragma unroll
                    for (int nt = 0; nt < 8; nt++)
                        mma8(acc[mt][nt], afr[mt], bfr[nt]);
            }
            __syncthreads();
        }

        int m0 = tile << 7;
#pragma unroll
        for (int mt = 0; mt < 2; mt++) {
            if (CENTER) {
                int m0r = m0 + wm * 32 + mt * 16 + grp;
                int m1r = m0r + 8;
#pragma unroll
                for (int nt = 0; nt < 8; nt++) {
                    int col = wn * 64 + nt * 8 + tig * 2;
                    if (m0r < N_ACT)
                        *(float2*)&out[(long)m0r * Cc + col] =
                            make_float2(acc[mt][nt][0], acc[mt][nt][1]);
                    if (m1r < N_ACT)
                        *(float2*)&out[(long)m1r * Cc + col] =
                            make_float2(acc[mt][nt][2], acc[mt][nt][3]);
                }
            } else {
                int ro0 = ro[mt][0], ro1 = ro[mt][1];
#pragma unroll
                for (int nt = 0; nt < 8; nt++) {
                    int col = wn * 64 + nt * 8 + tig * 2;
                    if (ro0 >= 0)
                        red_add2(&out[(long)ro0 * Cc + col], acc[mt][nt][0], acc[mt][nt][1]);
                    if (ro1 >= 0)
                        red_add2(&out[(long)ro1 * Cc + col], acc[mt][nt][2], acc[mt][nt][3]);
                }
            }
        }
    }
    asm volatile("cp.async.wait_group 0;" ::: "memory");
}

// ---------------- per-channel stats + fused finalize (last block) ------------
template <bool RESETCNT>
__global__ void __launch_bounds__(256) stats_k(
    const float* __restrict__ y,
    const float* __restrict__ gamma, const float* __restrict__ beta)
{
    __shared__ float ssum[8][32][4];
    __shared__ float ssq [8][32][4];
    __shared__ int lastFlag;

    pdl_wait();
    pdl_trigger();

    int tid = threadIdx.x;
    int wid = tid >> 5;
    int c4  = tid & 31;

    float4 s = make_float4(0.f, 0.f, 0.f, 0.f);
    float4 q = make_float4(0.f, 0.f, 0.f, 0.f);
#pragma unroll 4
    for (int r = blockIdx.x * 8 + wid; r < N_ACT; r += gridDim.x * 8) {
        float4 v = *(const float4*)&y[(long)r * Cc + c4 * 4];
        s.x += v.x; s.y += v.y; s.z += v.z; s.w += v.w;
        q.x += v.x * v.x; q.y += v.y * v.y; q.z += v.z * v.z; q.w += v.w * v.w;
    }
    ssum[wid][c4][0] = s.x; ssum[wid][c4][1] = s.y;
    ssum[wid][c4][2] = s.z; ssum[wid][c4][3] = s.w;
    ssq [wid][c4][0] = q.x; ssq [wid][c4][1] = q.y;
    ssq [wid][c4][2] = q.z; ssq [wid][c4][3] = q.w;
    __syncthreads();

    if (tid < 128) {
        int cg = tid >> 2, j = tid & 3;
        float ts = 0.f, tq = 0.f;
#pragma unroll
        for (int w = 0; w < 8; w++) { ts += ssum[w][cg][j]; tq += ssq[w][cg][j]; }
        atomicAdd(&g_sum[tid], ts);
        atomicAdd(&g_sq [tid], tq);
    }
    __threadfence();
    if (tid == 0) {
        int old = atomicAdd(&g_done, 1);
        lastFlag = (old == (int)gridDim.x - 1);
    }
    __syncthreads();
    if (lastFlag) {
        if (tid < 128) {
            float sv = *((volatile float*)&g_sum[tid]);
            float qv = *((volatile float*)&g_sq [tid]);
            float mean = sv * (1.f / N_ACT);
            float var  = qv * (1.f / N_ACT) - mean * mean;
            float istd = rsqrtf(var + EPSV);
            float sc = gamma[tid] * istd;
            g_scale[tid] = sc;
            g_shift[tid] = beta[tid] - mean * sc;
            g_sum[tid] = 0.f;
            g_sq [tid] = 0.f;
        }
        if (RESETCNT && tid >= 128 && tid < 128 + NTAPS)
            g_cnt[tid - 128] = 0;
        __threadfence();
        if (tid == 0) g_done = 0;
    }
}

__global__ __launch_bounds__(256) void final_k(
    const float* __restrict__ y, const float* __restrict__ x, float* __restrict__ outp)
{
    pdl_wait();
    pdl_trigger();
    int i = blockIdx.x * blockDim.x + threadIdx.x;
    if (i >= N_ACT * Cc / 4) return;
    int c4 = (i & 31) * 4;
    float4 v  = ((const float4*)y)[i];
    float4 xv = ((const float4*)x)[i];
    float4 sc = *(const float4*)&g_scale[c4];
    float4 sh = *(const float4*)&g_shift[c4];
    float4 o;
    o.x = fmaxf(v.x * sc.x + sh.x + xv.x, 0.f);
    o.y = fmaxf(v.y * sc.y + sh.y + xv.y, 0.f);
    o.z = fmaxf(v.z * sc.z + sh.z + xv.z, 0.f);
    o.w = fmaxf(v.w * sc.w + sh.w + xv.w, 0.f);
    ((float4*)outp)[i] = o;
}

// ---------------- launch ------------------------------------------------------
template <typename K, typename... Args>
static void pdl_launch(K kern, dim3 grid, dim3 block, size_t smem, Args... args) {
    cudaLaunchConfig_t cfg = {};
    cfg.gridDim = grid;
    cfg.blockDim = block;
    cfg.dynamicSmemBytes = smem;
    cfg.stream = 0;
    cudaLaunchAttribute attr[1];
    attr[0].id = cudaLaunchAttributeProgrammaticStreamSerialization;
    attr[0].val.programmaticStreamSerializationAllowed = 1;
    cfg.attrs = attr;
    cfg.numAttrs = 1;
    cudaLaunchKernelEx(&cfg, kern, args...);
}

extern "C" void kernel_launch(void* const* d_in, const int* in_sizes, int n_in,
                              void* d_out, int out_size)
{
    const float* x   = (const float*)d_in[0];
    const int*   nbr = (const int*)  d_in[1];
    const float* W1  = (const float*)d_in[2];
    const float* g1  = (const float*)d_in[3];
    const float* b1  = (const float*)d_in[4];
    const float* W2  = (const float*)d_in[5];
    const float* g2  = (const float*)d_in[6];
    const float* b2  = (const float*)d_in[7];
    float* out = (float*)d_out;

    float* buf1; cudaGetSymbolAddress((void**)&buf1, g_buf1);
    float* buf2; cudaGetSymbolAddress((void**)&buf2, g_buf2);

    const int SMEM = (WP_FLOATS + 2 * AS_STAGE) * 4 + 256 * 4 + 2 * 128 * 4;
    cudaFuncSetAttribute(conv_mma_k<true,  false, true >, cudaFuncAttributeMaxDynamicSharedMemorySize, SMEM);
    cudaFuncSetAttribute(conv_mma_k<false, false, false>, cudaFuncAttributeMaxDynamicSharedMemorySize, SMEM);
    cudaFuncSetAttribute(conv_mma_k<true,  true,  false>, cudaFuncAttributeMaxDynamicSharedMemorySize, SMEM);
    cudaFuncSetAttribute(conv_mma_k<false, true,  false>, cudaFuncAttributeMaxDynamicSharedMemorySize, SMEM);

    const int ewBlocks = (N_ACT * Cc / 4 + 255) / 256;

    // ---- layer 1 (rulebook built inside the center conv prologue) ----
    pdl_launch(conv_mma_k<true,  false, true >, dim3(304), dim3(256), SMEM,
               x, W1 + 4 * Cc * Cc, buf1, nbr);
    pdl_launch(conv_mma_k<false, false, false>, dim3(38, NTAPS), dim3(256), SMEM,
               x, W1, buf1, (const int*)nullptr);
    pdl_launch(stats_k<false>, dim3(304), dim3(256), 0, (const float*)buf1, g1, b1);

    // ---- layer 2 (BN+ReLU of layer 1 fused into A loads) ----
    pdl_launch(conv_mma_k<true,  true,  false>, dim3(304), dim3(256), SMEM,
               (const float*)buf1, W2 + 4 * Cc * Cc, buf2, (const int*)nullptr);
    pdl_launch(conv_mma_k<false, true,  false>, dim3(38, NTAPS), dim3(256), SMEM,
               (const float*)buf1, W2, buf2, (const int*)nullptr);
    pdl_launch(stats_k<true>, dim3(304), dim3(256), 0, (const float*)buf2, g2, b2);
    pdl_launch(final_k, dim3(ewBlocks), dim3(256), 0, (const float*)buf2, x, out);
}